// round 11
// baseline (speedup 1.0000x reference)
#include <cuda_runtime.h>
#include <cstdint>

using ull = unsigned long long;
#define NTHREADS 512

__device__ __forceinline__ void fma2(ull& d, ull a, ull b) {
    asm("fma.rn.f32x2 %0, %1, %2, %0;" : "+l"(d) : "l"(a), "l"(b));
}
__device__ __forceinline__ ull dup2(float x) {
    ull d; unsigned xi = __float_as_uint(x);
    asm("mov.b64 %0, {%1, %1};" : "=l"(d) : "r"(xi));
    return d;
}
__device__ __forceinline__ void cp_async8(void* dst, const void* src) {
    unsigned s = (unsigned)__cvta_generic_to_shared(dst);
    asm volatile("cp.async.ca.shared.global [%0], [%1], 8;" :: "r"(s), "l"(src));
}
__device__ __forceinline__ void cp_commit() { asm volatile("cp.async.commit_group;"); }
__device__ __forceinline__ void cp_wait1() { asm volatile("cp.async.wait_group 1;" ::: "memory"); }

// ---------------------------------------------------------------------------
// 0e: out[n,o] = sum_i x[n,i] * w[o,i] + bias[o];  I=O=128, M=1
// ---------------------------------------------------------------------------
__global__ __launch_bounds__(NTHREADS, 1)
void k0e(const float* __restrict__ x, const float* __restrict__ w,
         const float* __restrict__ bias, float* __restrict__ out, int N) {
    constexpr int K = 128, O = 128, TILE = 128, XROW = 130, WROW = 132;
    constexpr int WS = K * WROW;       // 16896 floats
    constexpr int XB = TILE * XROW;    // 16640 floats
    constexpr int CH = TILE * (K / 2); // 8192 8B chunks/tile

    extern __shared__ float sm[];
    float* ws = sm;
    float* xbuf0 = sm + WS;
    float* xbuf1 = sm + WS + XB;
    float* bs = sm + WS + 2 * XB;

    int tid = threadIdx.x;
    for (int idx = tid; idx < O * K; idx += NTHREADS)
        ws[(idx & (K - 1)) * WROW + (idx >> 7)] = w[idx];   // ws[i][o] = w[o][i]
    if (tid < O) bs[tid] = bias[tid];

    int warp = tid >> 5, lane = tid & 31;
    int node = (warp & 3) * 32 + lane;     // 0..127 within tile
    int ob2  = (warp >> 2) * 16;           // ull offset: 16 pairs = 32 outputs

    int ntiles = (N + TILE - 1) / TILE;
    int t0 = blockIdx.x;

    if (t0 < ntiles) {
        long long base = (long long)t0 * TILE;
        for (int c = tid; c < CH; c += NTHREADS) {
            int nd = c >> 6, cq = c & 63;
            long long n = base + nd;
            if (n < N) cp_async8(xbuf0 + nd * XROW + cq * 2, x + n * K + cq * 2);
        }
    }
    cp_commit();

    int par = 0;
    for (int t = t0; t < ntiles; t += gridDim.x, par ^= 1) {
        int tn = t + gridDim.x;
        if (tn < ntiles) {
            long long base = (long long)tn * TILE;
            float* dst = par ? xbuf0 : xbuf1;
            for (int c = tid; c < CH; c += NTHREADS) {
                int nd = c >> 6, cq = c & 63;
                long long n = base + nd;
                if (n < N) cp_async8(dst + nd * XROW + cq * 2, x + n * K + cq * 2);
            }
        }
        cp_commit();
        cp_wait1();
        __syncthreads();

        float* xa = par ? xbuf1 : xbuf0;
        const float* xrow = xa + node * XROW;

        ull acc[16];
        const ull* bs2 = (const ull*)bs;
        #pragma unroll
        for (int j = 0; j < 16; j++) acc[j] = bs2[ob2 + j];

        #pragma unroll 2
        for (int k = 0; k < K; k += 2) {
            float2 xv = *(const float2*)(xrow + k);
            ull x0 = dup2(xv.x), x1 = dup2(xv.y);
            const ull* w0 = (const ull*)(ws + k * WROW) + ob2;
            const ull* w1 = (const ull*)(ws + (k + 1) * WROW) + ob2;
            #pragma unroll
            for (int j = 0; j < 16; j++) fma2(acc[j], x0, w0[j]);
            #pragma unroll
            for (int j = 0; j < 16; j++) fma2(acc[j], x1, w1[j]);
        }
        __syncthreads();

        // stage outputs into xa (stride XROW), then coalesced copy-out
        ull* yrow = (ull*)(xa + node * XROW) + ob2;
        #pragma unroll
        for (int j = 0; j < 16; j++) yrow[j] = acc[j];
        __syncthreads();

        long long base = (long long)t * TILE;
        for (int idx = tid; idx < TILE * O; idx += NTHREADS) {
            int nd = idx >> 7, o = idx & 127;
            long long n = base + nd;
            if (n < N) out[n * 480 + o] = xa[nd * XROW + o];
        }
        __syncthreads();
    }
}

// ---------------------------------------------------------------------------
// 1o: out[n,o,m] = sum_i x[n,i,m] * w[o,i,m];  I=O=64, M=3
// ---------------------------------------------------------------------------
__global__ __launch_bounds__(NTHREADS, 1)
void k1o(const float* __restrict__ x, const float* __restrict__ w,
         float* __restrict__ out, int N) {
    constexpr int I = 64, O = 64, K = 192, TILE = 64, XROW = 194, WROW = 68;
    constexpr int WS = K * WROW;       // 13056
    constexpr int XB = TILE * XROW;    // 12416
    constexpr int CH = TILE * (K / 2); // 6144

    extern __shared__ float sm[];
    float* ws = sm;
    float* xbuf0 = sm + WS;
    float* xbuf1 = sm + WS + XB;

    int tid = threadIdx.x;
    for (int idx = tid; idx < O * K; idx += NTHREADS)
        ws[(idx % K) * WROW + (idx / K)] = w[idx];   // ws[i*3+m][o]

    int warp = tid >> 5, lane = tid & 31;
    int node = (warp & 1) * 32 + lane;   // 0..63
    int ob2  = (warp >> 1) * 4;          // 4 pairs = 8 outputs

    int ntiles = (N + TILE - 1) / TILE;
    int t0 = blockIdx.x;

    if (t0 < ntiles) {
        long long base = (long long)t0 * TILE;
        for (int c = tid; c < CH; c += NTHREADS) {
            int nd = c / 96, cq = c % 96;
            long long n = base + nd;
            if (n < N) cp_async8(xbuf0 + nd * XROW + cq * 2, x + n * K + cq * 2);
        }
    }
    cp_commit();

    int par = 0;
    for (int t = t0; t < ntiles; t += gridDim.x, par ^= 1) {
        int tn = t + gridDim.x;
        if (tn < ntiles) {
            long long base = (long long)tn * TILE;
            float* dst = par ? xbuf0 : xbuf1;
            for (int c = tid; c < CH; c += NTHREADS) {
                int nd = c / 96, cq = c % 96;
                long long n = base + nd;
                if (n < N) cp_async8(dst + nd * XROW + cq * 2, x + n * K + cq * 2);
            }
        }
        cp_commit();
        cp_wait1();
        __syncthreads();

        float* xa = par ? xbuf1 : xbuf0;
        const float* xrow = xa + node * XROW;

        ull acc[3][4];
        #pragma unroll
        for (int m = 0; m < 3; m++)
            #pragma unroll
            for (int j = 0; j < 4; j++) acc[m][j] = 0ull;

        #pragma unroll 1
        for (int i = 0; i < I; i += 2) {
            // pair (i, i+1) covers x offsets 3*i .. 3*i+5
            float2 a = *(const float2*)(xrow + 3 * i);
            float2 b = *(const float2*)(xrow + 3 * i + 2);
            float2 c = *(const float2*)(xrow + 3 * i + 4);
            ull xd[6];
            xd[0] = dup2(a.x); xd[1] = dup2(a.y); xd[2] = dup2(b.x);
            xd[3] = dup2(b.y); xd[4] = dup2(c.x); xd[5] = dup2(c.y);
            #pragma unroll
            for (int s = 0; s < 2; s++)
                #pragma unroll
                for (int m = 0; m < 3; m++) {
                    const ull* wr = (const ull*)(ws + ((i + s) * 3 + m) * WROW) + ob2;
                    #pragma unroll
                    for (int j = 0; j < 4; j++) fma2(acc[m][j], xd[s * 3 + m], wr[j]);
                }
        }
        __syncthreads();

        float* yrow = xa + node * XROW;
        #pragma unroll
        for (int m = 0; m < 3; m++)
            #pragma unroll
            for (int j = 0; j < 4; j++) {
                int o = (ob2 + j) * 2;
                yrow[o * 3 + m]       = __uint_as_float((unsigned)acc[m][j]);
                yrow[(o + 1) * 3 + m] = __uint_as_float((unsigned)(acc[m][j] >> 32));
            }
        __syncthreads();

        long long base = (long long)t * TILE;
        for (int idx = tid; idx < TILE * 192; idx += NTHREADS) {
            int nd = idx / 192, f = idx % 192;
            long long n = base + nd;
            if (n < N) out[n * 480 + 128 + f] = xa[nd * XROW + f];
        }
        __syncthreads();
    }
}

// ---------------------------------------------------------------------------
// 2e: out[n,o,m] = sum_i x[n,i,m] * w[o,i,m];  I=O=32, M=5
// ---------------------------------------------------------------------------
__global__ __launch_bounds__(NTHREADS, 1)
void k2e(const float* __restrict__ x, const float* __restrict__ w,
         float* __restrict__ out, int N) {
    constexpr int I = 32, O = 32, K = 160, TILE = 64, XROW = 162, WROW = 36;
    constexpr int WS = K * WROW;       // 5760
    constexpr int XB = TILE * XROW;    // 10368
    constexpr int CH = TILE * (K / 2); // 5120

    extern __shared__ float sm[];
    float* ws = sm;
    float* xbuf0 = sm + WS;
    float* xbuf1 = sm + WS + XB;

    int tid = threadIdx.x;
    for (int idx = tid; idx < O * K; idx += NTHREADS)
        ws[(idx % K) * WROW + (idx / K)] = w[idx];   // ws[i*5+m][o]

    int warp = tid >> 5, lane = tid & 31;
    int node = (warp & 1) * 32 + lane;   // 0..63
    int ob2  = (warp >> 1) * 2;          // 2 pairs = 4 outputs

    int ntiles = (N + TILE - 1) / TILE;
    int t0 = blockIdx.x;

    if (t0 < ntiles) {
        long long base = (long long)t0 * TILE;
        for (int c = tid; c < CH; c += NTHREADS) {
            int nd = c / 80, cq = c % 80;
            long long n = base + nd;
            if (n < N) cp_async8(xbuf0 + nd * XROW + cq * 2, x + n * K + cq * 2);
        }
    }
    cp_commit();

    int par = 0;
    for (int t = t0; t < ntiles; t += gridDim.x, par ^= 1) {
        int tn = t + gridDim.x;
        if (tn < ntiles) {
            long long base = (long long)tn * TILE;
            float* dst = par ? xbuf0 : xbuf1;
            for (int c = tid; c < CH; c += NTHREADS) {
                int nd = c / 80, cq = c % 80;
                long long n = base + nd;
                if (n < N) cp_async8(dst + nd * XROW + cq * 2, x + n * K + cq * 2);
            }
        }
        cp_commit();
        cp_wait1();
        __syncthreads();

        float* xa = par ? xbuf1 : xbuf0;
        const float* xrow = xa + node * XROW;

        ull acc[5][2];
        #pragma unroll
        for (int m = 0; m < 5; m++) { acc[m][0] = 0ull; acc[m][1] = 0ull; }

        #pragma unroll 1
        for (int i = 0; i < I; i += 2) {
            // pair (i, i+1) covers x offsets 5*i .. 5*i+9  (FIX: was 10*i, OOB)
            ull xd[10];
            #pragma unroll
            for (int u = 0; u < 5; u++) {
                float2 v = *(const float2*)(xrow + 5 * i + 2 * u);
                xd[2 * u]     = dup2(v.x);
                xd[2 * u + 1] = dup2(v.y);
            }
            // xd flat index g = s*5 + m maps to element (i + s, m)
            #pragma unroll
            for (int s = 0; s < 2; s++)
                #pragma unroll
                for (int m = 0; m < 5; m++) {
                    const ull* wr = (const ull*)(ws + ((i + s) * 5 + m) * WROW) + ob2;
                    fma2(acc[m][0], xd[s * 5 + m], wr[0]);
                    fma2(acc[m][1], xd[s * 5 + m], wr[1]);
                }
        }
        __syncthreads();

        float* yrow = xa + node * XROW;
        #pragma unroll
        for (int m = 0; m < 5; m++)
            #pragma unroll
            for (int j = 0; j < 2; j++) {
                int o = (ob2 + j) * 2;
                yrow[o * 5 + m]       = __uint_as_float((unsigned)acc[m][j]);
                yrow[(o + 1) * 5 + m] = __uint_as_float((unsigned)(acc[m][j] >> 32));
            }
        __syncthreads();

        long long base = (long long)t * TILE;
        for (int idx = tid; idx < TILE * 160; idx += NTHREADS) {
            int nd = idx / 160, f = idx % 160;
            long long n = base + nd;
            if (n < N) out[n * 480 + 320 + f] = xa[nd * XROW + f];
        }
        __syncthreads();
    }
}

// ---------------------------------------------------------------------------
extern "C" void kernel_launch(void* const* d_in, const int* in_sizes, int n_in,
                              void* d_out, int out_size) {
    const float* x0e  = (const float*)d_in[0];
    const float* x1o  = (const float*)d_in[1];
    const float* x2e  = (const float*)d_in[2];
    const float* w0e  = (const float*)d_in[3];
    const float* w1o  = (const float*)d_in[4];
    const float* w2e  = (const float*)d_in[5];
    const float* bias = (const float*)d_in[6];
    float* out = (float*)d_out;
    int N = in_sizes[0] / 128;

    int smem0 = (16896 + 2 * 16640 + 128) * 4;  // 201216 B
    int smem1 = (13056 + 2 * 12416) * 4;        // 151552 B
    int smem2 = (5760  + 2 * 10368) * 4;        // 105984 B

    cudaFuncSetAttribute(k0e, cudaFuncAttributeMaxDynamicSharedMemorySize, smem0);
    cudaFuncSetAttribute(k1o, cudaFuncAttributeMaxDynamicSharedMemorySize, smem1);
    cudaFuncSetAttribute(k2e, cudaFuncAttributeMaxDynamicSharedMemorySize, smem2);

    k0e<<<152, NTHREADS, smem0>>>(x0e, w0e, bias, out, N);
    k1o<<<152, NTHREADS, smem1>>>(x1o, w1o, out, N);
    k2e<<<152, NTHREADS, smem2>>>(x2e, w2e, out, N);
}

// round 12
// speedup vs baseline: 1.2052x; 1.2052x over previous
#include <cuda_runtime.h>
#include <cstdint>

using ull = unsigned long long;
#define NTHREADS 512

__device__ __forceinline__ void fma2(ull& d, ull a, ull b) {
    asm("fma.rn.f32x2 %0, %1, %2, %0;" : "+l"(d) : "l"(a), "l"(b));
}
__device__ __forceinline__ ull dup2(float x) {
    ull d; unsigned xi = __float_as_uint(x);
    asm("mov.b64 %0, {%1, %1};" : "=l"(d) : "r"(xi));
    return d;
}
__device__ __forceinline__ float ulo(ull v) { return __uint_as_float((unsigned)v); }
__device__ __forceinline__ float uhi(ull v) { return __uint_as_float((unsigned)(v >> 32)); }
__device__ __forceinline__ void cp_async8(void* dst, const void* src) {
    unsigned s = (unsigned)__cvta_generic_to_shared(dst);
    asm volatile("cp.async.ca.shared.global [%0], [%1], 8;" :: "r"(s), "l"(src));
}
__device__ __forceinline__ void cp_commit() { asm volatile("cp.async.commit_group;"); }
__device__ __forceinline__ void cp_wait1() { asm volatile("cp.async.wait_group 1;" ::: "memory"); }

// ---------------------------------------------------------------------------
// 0e: out[n,o] = sum_i x[n,i] * w[o,i] + bias[o];  I=O=128, M=1
// thread: 2 nodes x 8 output-pairs (16 outputs)
// ---------------------------------------------------------------------------
__global__ __launch_bounds__(NTHREADS, 1)
void k0e(const float* __restrict__ x, const float* __restrict__ w,
         const float* __restrict__ bias, float* __restrict__ out, int N) {
    constexpr int K = 128, O = 128, TILE = 128, XROW = 130, WROW = 132;
    constexpr int WS = K * WROW;       // 16896 floats
    constexpr int XB = TILE * XROW;    // 16640 floats
    constexpr int CH = TILE * (K / 2); // 8192 8B chunks/tile

    extern __shared__ float sm[];
    float* ws = sm;
    float* xbuf0 = sm + WS;
    float* xbuf1 = sm + WS + XB;
    float* bs = sm + WS + 2 * XB;

    int tid = threadIdx.x;
    for (int idx = tid; idx < O * K; idx += NTHREADS)
        ws[(idx & (K - 1)) * WROW + (idx >> 7)] = w[idx];   // ws[i][o] = w[o][i]
    if (tid < O) bs[tid] = bias[tid];

    int warp = tid >> 5, lane = tid & 31;
    int grp  = warp >> 1;            // 0..7, uniform per warp -> broadcast w loads
    int ob2  = grp * 8;              // ull index: 8 pairs = outputs [16g, 16g+16)
    int na   = (warp & 1) * 32 + lane;  // 0..63
    int nb   = na + 64;

    int ntiles = (N + TILE - 1) / TILE;
    int t0 = blockIdx.x;

    if (t0 < ntiles) {
        long long base = (long long)t0 * TILE;
        for (int c = tid; c < CH; c += NTHREADS) {
            int nd = c >> 6, cq = c & 63;
            long long n = base + nd;
            if (n < N) cp_async8(xbuf0 + nd * XROW + cq * 2, x + n * K + cq * 2);
        }
    }
    cp_commit();

    int par = 0;
    for (int t = t0; t < ntiles; t += gridDim.x, par ^= 1) {
        int tn = t + gridDim.x;
        if (tn < ntiles) {
            long long base = (long long)tn * TILE;
            float* dst = par ? xbuf0 : xbuf1;
            for (int c = tid; c < CH; c += NTHREADS) {
                int nd = c >> 6, cq = c & 63;
                long long n = base + nd;
                if (n < N) cp_async8(dst + nd * XROW + cq * 2, x + n * K + cq * 2);
            }
        }
        cp_commit();
        cp_wait1();
        __syncthreads();

        float* xa = par ? xbuf1 : xbuf0;
        const float* xra = xa + na * XROW;
        const float* xrb = xa + nb * XROW;

        ull acc0[8], acc1[8];
        const ull* bs2 = (const ull*)bs;
        #pragma unroll
        for (int j = 0; j < 8; j++) { acc0[j] = bs2[ob2 + j]; acc1[j] = bs2[ob2 + j]; }

        #pragma unroll 4
        for (int k = 0; k < K; k += 2) {
            float2 va = *(const float2*)(xra + k);
            float2 vb = *(const float2*)(xrb + k);
            ull a0 = dup2(va.x), a1 = dup2(va.y);
            ull b0 = dup2(vb.x), b1 = dup2(vb.y);
            const ulonglong2* w0 = (const ulonglong2*)(ws + k * WROW) + grp * 4;
            const ulonglong2* w1 = (const ulonglong2*)(ws + (k + 1) * WROW) + grp * 4;
            #pragma unroll
            for (int j = 0; j < 4; j++) {
                ulonglong2 u = w0[j];
                fma2(acc0[2*j],   a0, u.x); fma2(acc0[2*j+1], a0, u.y);
                fma2(acc1[2*j],   b0, u.x); fma2(acc1[2*j+1], b0, u.y);
            }
            #pragma unroll
            for (int j = 0; j < 4; j++) {
                ulonglong2 u = w1[j];
                fma2(acc0[2*j],   a1, u.x); fma2(acc0[2*j+1], a1, u.y);
                fma2(acc1[2*j],   b1, u.x); fma2(acc1[2*j+1], b1, u.y);
            }
        }

        long long base = (long long)t * TILE;
        long long n_a = base + na, n_b = base + nb;
        if (n_a < N) {
            ulonglong2* d = (ulonglong2*)(out + n_a * 480 + grp * 16);
            #pragma unroll
            for (int j = 0; j < 4; j++) d[j] = make_ulonglong2(acc0[2*j], acc0[2*j+1]);
        }
        if (n_b < N) {
            ulonglong2* d = (ulonglong2*)(out + n_b * 480 + grp * 16);
            #pragma unroll
            for (int j = 0; j < 4; j++) d[j] = make_ulonglong2(acc1[2*j], acc1[2*j+1]);
        }
        __syncthreads();   // protect xa from next iteration's prefetch
    }
}

// ---------------------------------------------------------------------------
// 1o: out[n,o,m] = sum_i x[n,i,m] * w[o,i,m];  I=O=64, M=3
// thread: 2 nodes x 2 output-pairs (4 outputs x 3 m)
// ---------------------------------------------------------------------------
__global__ __launch_bounds__(NTHREADS, 1)
void k1o(const float* __restrict__ x, const float* __restrict__ w,
         float* __restrict__ out, int N) {
    constexpr int I = 64, O = 64, K = 192, TILE = 64, XROW = 194, WROW = 68;
    constexpr int WS = K * WROW;       // 13056
    constexpr int XB = TILE * XROW;    // 12416
    constexpr int CH = TILE * (K / 2); // 6144

    extern __shared__ float sm[];
    float* ws = sm;
    float* xbuf0 = sm + WS;
    float* xbuf1 = sm + WS + XB;

    int tid = threadIdx.x;
    for (int idx = tid; idx < O * K; idx += NTHREADS)
        ws[(idx % K) * WROW + (idx / K)] = w[idx];   // ws[i*3+m][o]

    int warp = tid >> 5, lane = tid & 31;
    int na = lane, nb = lane + 32;
    // warp -> 2 pairs = outputs [4w, 4w+4); ulonglong2 index = warp

    int ntiles = (N + TILE - 1) / TILE;
    int t0 = blockIdx.x;

    if (t0 < ntiles) {
        long long base = (long long)t0 * TILE;
        for (int c = tid; c < CH; c += NTHREADS) {
            int nd = c / 96, cq = c % 96;
            long long n = base + nd;
            if (n < N) cp_async8(xbuf0 + nd * XROW + cq * 2, x + n * K + cq * 2);
        }
    }
    cp_commit();

    int par = 0;
    for (int t = t0; t < ntiles; t += gridDim.x, par ^= 1) {
        int tn = t + gridDim.x;
        if (tn < ntiles) {
            long long base = (long long)tn * TILE;
            float* dst = par ? xbuf0 : xbuf1;
            for (int c = tid; c < CH; c += NTHREADS) {
                int nd = c / 96, cq = c % 96;
                long long n = base + nd;
                if (n < N) cp_async8(dst + nd * XROW + cq * 2, x + n * K + cq * 2);
            }
        }
        cp_commit();
        cp_wait1();
        __syncthreads();

        float* xa = par ? xbuf1 : xbuf0;
        const float* xra = xa + na * XROW;
        const float* xrb = xa + nb * XROW;

        ull acc[2][3][2];
        #pragma unroll
        for (int n2 = 0; n2 < 2; n2++)
            #pragma unroll
            for (int m = 0; m < 3; m++) { acc[n2][m][0] = 0ull; acc[n2][m][1] = 0ull; }

        #pragma unroll 2
        for (int i = 0; i < I; i += 2) {
            const float* pa = xra + 3 * i;
            const float* pb = xrb + 3 * i;
            float2 a01 = *(const float2*)(pa);
            float2 a23 = *(const float2*)(pa + 2);
            float2 a45 = *(const float2*)(pa + 4);
            float2 b01 = *(const float2*)(pb);
            float2 b23 = *(const float2*)(pb + 2);
            float2 b45 = *(const float2*)(pb + 4);
            ull xda[6] = { dup2(a01.x), dup2(a01.y), dup2(a23.x),
                           dup2(a23.y), dup2(a45.x), dup2(a45.y) };
            ull xdb[6] = { dup2(b01.x), dup2(b01.y), dup2(b23.x),
                           dup2(b23.y), dup2(b45.x), dup2(b45.y) };
            #pragma unroll
            for (int s = 0; s < 2; s++)
                #pragma unroll
                for (int m = 0; m < 3; m++) {
                    ulonglong2 u = *((const ulonglong2*)(ws + ((i + s) * 3 + m) * WROW) + warp);
                    ull va = xda[s * 3 + m], vb = xdb[s * 3 + m];
                    fma2(acc[0][m][0], va, u.x); fma2(acc[0][m][1], va, u.y);
                    fma2(acc[1][m][0], vb, u.x); fma2(acc[1][m][1], vb, u.y);
                }
        }

        long long base = (long long)t * TILE;
        #pragma unroll
        for (int n2 = 0; n2 < 2; n2++) {
            long long n = base + (n2 ? nb : na);
            if (n < N) {
                float4 y4[3];
                float* y = (float*)y4;
                #pragma unroll
                for (int m = 0; m < 3; m++)
                    #pragma unroll
                    for (int p = 0; p < 2; p++) {
                        y[(2 * p) * 3 + m]     = ulo(acc[n2][m][p]);
                        y[(2 * p + 1) * 3 + m] = uhi(acc[n2][m][p]);
                    }
                float4* d = (float4*)(out + n * 480 + 128 + 12 * warp);
                #pragma unroll
                for (int q = 0; q < 3; q++) d[q] = y4[q];
            }
        }
        __syncthreads();
    }
}

// ---------------------------------------------------------------------------
// 2e: out[n,o,m] = sum_i x[n,i,m] * w[o,i,m];  I=O=32, M=5
// TILE=128 nodes; thread: 1 node x 4 output-pairs (8 outputs x 5 m)
// ---------------------------------------------------------------------------
__global__ __launch_bounds__(NTHREADS, 1)
void k2e(const float* __restrict__ x, const float* __restrict__ w,
         float* __restrict__ out, int N) {
    constexpr int I = 32, O = 32, K = 160, TILE = 128, XROW = 162, WROW = 36;
    constexpr int WS = K * WROW;       // 5760
    constexpr int XB = TILE * XROW;    // 20736
    constexpr int CH = TILE * (K / 2); // 10240

    extern __shared__ float sm[];
    float* ws = sm;
    float* xbuf0 = sm + WS;
    float* xbuf1 = sm + WS + XB;

    int tid = threadIdx.x;
    for (int idx = tid; idx < O * K; idx += NTHREADS)
        ws[(idx % K) * WROW + (idx / K)] = w[idx];   // ws[i*5+m][o]

    int warp = tid >> 5, lane = tid & 31;
    int grp  = warp >> 2;                 // 0..3, uniform per warp
    int node = (warp & 3) * 32 + lane;    // 0..127
    // grp -> 4 pairs = outputs [8g, 8g+8); ulonglong2 base index = grp*2

    int ntiles = (N + TILE - 1) / TILE;
    int t0 = blockIdx.x;

    if (t0 < ntiles) {
        long long base = (long long)t0 * TILE;
        for (int c = tid; c < CH; c += NTHREADS) {
            int nd = c / 80, cq = c % 80;
            long long n = base + nd;
            if (n < N) cp_async8(xbuf0 + nd * XROW + cq * 2, x + n * K + cq * 2);
        }
    }
    cp_commit();

    int par = 0;
    for (int t = t0; t < ntiles; t += gridDim.x, par ^= 1) {
        int tn = t + gridDim.x;
        if (tn < ntiles) {
            long long base = (long long)tn * TILE;
            float* dst = par ? xbuf0 : xbuf1;
            for (int c = tid; c < CH; c += NTHREADS) {
                int nd = c / 80, cq = c % 80;
                long long n = base + nd;
                if (n < N) cp_async8(dst + nd * XROW + cq * 2, x + n * K + cq * 2);
            }
        }
        cp_commit();
        cp_wait1();
        __syncthreads();

        float* xa = par ? xbuf1 : xbuf0;
        const float* xrow = xa + node * XROW;

        ull acc[5][4];
        #pragma unroll
        for (int m = 0; m < 5; m++)
            #pragma unroll
            for (int p = 0; p < 4; p++) acc[m][p] = 0ull;

        #pragma unroll 2
        for (int i = 0; i < I; i += 2) {
            // pair (i, i+1): x offsets 5i .. 5i+9 (5i even since i even)
            ull xd[10];
            #pragma unroll
            for (int u = 0; u < 5; u++) {
                float2 v = *(const float2*)(xrow + 5 * i + 2 * u);
                xd[2 * u]     = dup2(v.x);
                xd[2 * u + 1] = dup2(v.y);
            }
            #pragma unroll
            for (int s = 0; s < 2; s++)
                #pragma unroll
                for (int m = 0; m < 5; m++) {
                    const ulonglong2* wr =
                        (const ulonglong2*)(ws + ((i + s) * 5 + m) * WROW) + grp * 2;
                    ull xv = xd[s * 5 + m];
                    ulonglong2 u0 = wr[0], u1 = wr[1];
                    fma2(acc[m][0], xv, u0.x); fma2(acc[m][1], xv, u0.y);
                    fma2(acc[m][2], xv, u1.x); fma2(acc[m][3], xv, u1.y);
                }
        }

        long long base = (long long)t * TILE;
        long long n = base + node;
        if (n < N) {
            float4 y4[10];
            float* y = (float*)y4;
            #pragma unroll
            for (int m = 0; m < 5; m++)
                #pragma unroll
                for (int p = 0; p < 4; p++) {
                    y[(2 * p) * 5 + m]     = ulo(acc[m][p]);
                    y[(2 * p + 1) * 5 + m] = uhi(acc[m][p]);
                }
            float4* d = (float4*)(out + n * 480 + 320 + 40 * grp);
            #pragma unroll
            for (int q = 0; q < 10; q++) d[q] = y4[q];
        }
        __syncthreads();
    }
}

// ---------------------------------------------------------------------------
extern "C" void kernel_launch(void* const* d_in, const int* in_sizes, int n_in,
                              void* d_out, int out_size) {
    const float* x0e  = (const float*)d_in[0];
    const float* x1o  = (const float*)d_in[1];
    const float* x2e  = (const float*)d_in[2];
    const float* w0e  = (const float*)d_in[3];
    const float* w1o  = (const float*)d_in[4];
    const float* w2e  = (const float*)d_in[5];
    const float* bias = (const float*)d_in[6];
    float* out = (float*)d_out;
    int N = in_sizes[0] / 128;

    int smem0 = (16896 + 2 * 16640 + 128) * 4;  // 201216 B
    int smem1 = (13056 + 2 * 12416) * 4;        // 151552 B
    int smem2 = (5760  + 2 * 20736) * 4;        // 188928 B

    cudaFuncSetAttribute(k0e, cudaFuncAttributeMaxDynamicSharedMemorySize, smem0);
    cudaFuncSetAttribute(k1o, cudaFuncAttributeMaxDynamicSharedMemorySize, smem1);
    cudaFuncSetAttribute(k2e, cudaFuncAttributeMaxDynamicSharedMemorySize, smem2);

    k0e<<<152, NTHREADS, smem0>>>(x0e, w0e, bias, out, N);
    k1o<<<152, NTHREADS, smem1>>>(x1o, w1o, out, N);
    k2e<<<152, NTHREADS, smem2>>>(x2e, w2e, out, N);
}